// round 3
// baseline (speedup 1.0000x reference)
#include <cuda_runtime.h>
#include <cuda_bf16.h>
#include <stdint.h>

// ---------------- static scratch (allowed: __device__ globals) ----------------
#define KS   (1 << 19)     // voxel key space upper bound: 16 * 32^3 = 524288
#define NMAX (1 << 19)     // >= N = 400000
#define EMAX (1 << 22)     // >= E = 3200000
#define DD   64

__device__ int      g_qmax[3];
__device__ int      g_flags[KS];
__device__ int      g_rank[KS];
__device__ int      g_ukeys[KS];
__device__ int      g_pkey[NMAX];
__device__ int      g_pinv[NMAX];
__device__ float    g_possum[KS * 3];
__device__ int      g_pcount[KS];
__device__ unsigned g_xmax[(size_t)KS * DD];   // encoded float max per (voxel, d)
__device__ int      g_ucount[KS];
__device__ int      g_uoff[KS];
__device__ int      g_ucursor[KS];
__device__ int      g_ucnt2[KS];
__device__ int      g_uoff2[KS];
__device__ int      g_vbuf[EMAX];
__device__ int      g_bsums[512];
__device__ int      g_M;
__device__ int      g_Eu;

// order-preserving float <-> uint encode (monotonic; 0 < enc(any finite))
__device__ __forceinline__ unsigned encf(float f) {
    unsigned u = __float_as_uint(f);
    return (u & 0x80000000u) ? ~u : (u | 0x80000000u);
}
__device__ __forceinline__ float decf(unsigned u) {
    return __uint_as_float((u & 0x80000000u) ? (u & 0x7FFFFFFFu) : ~u);
}

// device-side selection of scan operands (NEVER pass __device__ symbols from host)
__device__ __forceinline__ const int* scan_in(int which) {
    return which == 0 ? g_flags : (which == 1 ? g_ucount : g_ucnt2);
}
__device__ __forceinline__ int* scan_out(int which) {
    return which == 0 ? g_rank : (which == 1 ? g_uoff : g_uoff2);
}

// ---------------- kernels ----------------

__global__ void k_zero1() {
    int i = blockIdx.x * blockDim.x + threadIdx.x;   // KS threads
    g_flags[i] = 0; g_ucount[i] = 0; g_ucursor[i] = 0; g_ucnt2[i] = 0;
    if (i < 3) g_qmax[i] = 0;
}

__global__ void k_qmax(const float* __restrict__ pos, int N) {
    __shared__ int sm[3];
    if (threadIdx.x < 3) sm[threadIdx.x] = 0;
    __syncthreads();
    int i = blockIdx.x * blockDim.x + threadIdx.x;
    if (i < N) {
#pragma unroll
        for (int j = 0; j < 3; j++) {
            int q = (int)floorf(pos[i * 3 + j] * 0.25f);
            atomicMax(&sm[j], q);
        }
    }
    __syncthreads();
    if (threadIdx.x < 3) atomicMax(&g_qmax[threadIdx.x], sm[threadIdx.x]);
}

__global__ void k_key(const float* __restrict__ pos, const int* __restrict__ batch, int N) {
    int i = blockIdx.x * blockDim.x + threadIdx.x;
    if (i >= N) return;
    int s0 = g_qmax[0] + 1, s1 = g_qmax[1] + 1, s2 = g_qmax[2] + 1;
    int q0 = (int)floorf(pos[i * 3 + 0] * 0.25f);
    int q1 = (int)floorf(pos[i * 3 + 1] * 0.25f);
    int q2 = (int)floorf(pos[i * 3 + 2] * 0.25f);
    int b  = batch[i];
    int key = ((b * s0 + q0) * s1 + q1) * s2 + q2;
    if (key < 0 || key >= KS) key = 0;   // defensive: never OOB
    g_pkey[i] = key;
    g_flags[key] = 1;
}

// --- exclusive scan over KS = 512 blocks x 1024 ---
__global__ void k_scanA(int which) {
    const int* __restrict__ in = scan_in(which);
    int* __restrict__ out = scan_out(which);
    __shared__ int ws[32];
    int t = threadIdx.x;
    int idx = blockIdx.x * 1024 + t;
    int v = in[idx];
    int inc = v;
#pragma unroll
    for (int o = 1; o < 32; o <<= 1) {
        int n = __shfl_up_sync(0xffffffffu, inc, o);
        if ((t & 31) >= o) inc += n;
    }
    if ((t & 31) == 31) ws[t >> 5] = inc;
    __syncthreads();
    if (t < 32) {
        int wv = ws[t]; int winc = wv;
#pragma unroll
        for (int o = 1; o < 32; o <<= 1) {
            int n = __shfl_up_sync(0xffffffffu, winc, o);
            if (t >= o) winc += n;
        }
        ws[t] = winc - wv;
    }
    __syncthreads();
    int off = ws[t >> 5];
    out[idx] = inc - v + off;
    if (t == 1023) g_bsums[blockIdx.x] = inc + off;
}

__global__ void k_scanB(int which) {      // single block, 512 threads
    __shared__ int ws[16];
    int t = threadIdx.x;
    int v = g_bsums[t];
    int inc = v;
#pragma unroll
    for (int o = 1; o < 32; o <<= 1) {
        int n = __shfl_up_sync(0xffffffffu, inc, o);
        if ((t & 31) >= o) inc += n;
    }
    if ((t & 31) == 31) ws[t >> 5] = inc;
    __syncthreads();
    if (t < 16) {
        int wv = ws[t]; int winc = wv;
#pragma unroll
        for (int o = 1; o < 16; o <<= 1) {
            int n = __shfl_up_sync(0x0000ffffu, winc, o);
            if (t >= o) winc += n;
        }
        ws[t] = winc - wv;
    }
    __syncthreads();
    int off = ws[t >> 5];
    g_bsums[t] = inc - v + off;
    if (t == 511) {
        int tot = inc + off;
        if (which == 0) g_M = tot;
        else if (which == 2) g_Eu = tot;
    }
}

__global__ void k_scanC(int which) {
    int* __restrict__ out = scan_out(which);
    int idx = blockIdx.x * blockDim.x + threadIdx.x;   // KS threads
    out[idx] += g_bsums[idx >> 10];
}

__global__ void k_ukeys() {
    int k = blockIdx.x * blockDim.x + threadIdx.x;
    if (g_flags[k]) g_ukeys[g_rank[k]] = k;
}

__global__ void k_zero2() {                // KS*64 threads
    int idx = blockIdx.x * blockDim.x + threadIdx.x;
    int M = g_M;
    if (idx < M * DD) g_xmax[idx] = 0;     // 0 < enc(any finite float)
    if (idx < M * 3)  g_possum[idx] = 0.0f;
    if (idx < M)      g_pcount[idx] = 0;
}

__global__ void k_accum_pos(const float* __restrict__ pos, int N) {
    int i = blockIdx.x * blockDim.x + threadIdx.x;
    if (i >= N) return;
    int inv = g_rank[g_pkey[i]];
    g_pinv[i] = inv;
    atomicAdd(&g_pcount[inv], 1);
    atomicAdd(&g_possum[inv * 3 + 0], pos[i * 3 + 0]);
    atomicAdd(&g_possum[inv * 3 + 1], pos[i * 3 + 1]);
    atomicAdd(&g_possum[inv * 3 + 2], pos[i * 3 + 2]);
}

__global__ void k_accum_x(const float* __restrict__ x, int ND) {
    int idx = blockIdx.x * blockDim.x + threadIdx.x;   // N*64 threads
    if (idx >= ND) return;
    int i = idx >> 6, d = idx & 63;
    int inv = g_pinv[i];
    atomicMax(&g_xmax[inv * DD + d], encf(x[idx]));
}

__global__ void k_ecount(const int* __restrict__ ei, int E) {
    int e = blockIdx.x * blockDim.x + threadIdx.x;
    if (e >= E) return;
    int u = g_pinv[ei[2 * e]];
    int v = g_pinv[ei[2 * e + 1]];
    if (u != v) atomicAdd(&g_ucount[u], 1);
}

__global__ void k_escatter(const int* __restrict__ ei, int E) {
    int e = blockIdx.x * blockDim.x + threadIdx.x;
    if (e >= E) return;
    int u = g_pinv[ei[2 * e]];
    int v = g_pinv[ei[2 * e + 1]];
    if (u != v) {
        int p = g_uoff[u] + atomicAdd(&g_ucursor[u], 1);
        if (p < EMAX) g_vbuf[p] = v;
    }
}

__global__ void k_sortuniq() {
    int u = blockIdx.x * blockDim.x + threadIdx.x;    // KS threads
    if (u >= g_M) return;
    int len = g_ucount[u], base = g_uoff[u];
    for (int i = 1; i < len; i++) {                   // insertion sort (avg len ~11)
        int key = g_vbuf[base + i];
        int j = i - 1;
        while (j >= 0 && g_vbuf[base + j] > key) { g_vbuf[base + j + 1] = g_vbuf[base + j]; j--; }
        g_vbuf[base + j + 1] = key;
    }
    int c = (len > 0) ? 1 : 0;
    for (int i = 1; i < len; i++) c += (g_vbuf[base + i] != g_vbuf[base + i - 1]);
    g_ucnt2[u] = c;
}

__global__ void k_write_main(float* __restrict__ out, long out_size) {
    long idx = (long)blockIdx.x * blockDim.x + threadIdx.x;  // KS*64 threads
    int M = g_M, Eu = g_Eu;
    if (idx < (long)M * DD && idx < out_size) out[idx] = decf(g_xmax[idx]);
    if (idx < (long)M * 3) {
        long o = (long)M * DD + idx;
        if (o < out_size) out[o] = g_possum[idx] / (float)g_pcount[idx / 3];
    }
    if (idx < M) {
        long ebase = (long)M * 67;
        long s = (long)(g_qmax[0] + 1) * (g_qmax[1] + 1) * (g_qmax[2] + 1);
        // self loops (appended after Eu dedup edges)
        long o1 = ebase + 2L * (Eu + idx);
        long o2 = ebase + 2L * (Eu + (long)M) + idx;   // new_batch slot
        if (o1 + 1 < out_size) {
            out[o1]     = (float)idx;
            out[o1 + 1] = (float)idx;
        }
        if (o2 < out_size) out[o2] = (float)(g_ukeys[idx] / (int)s);
    }
}

__global__ void k_write_edges(float* __restrict__ out, long out_size) {
    int u = blockIdx.x * blockDim.x + threadIdx.x;    // KS threads
    if (u >= g_M) return;
    int len = g_ucount[u], base = g_uoff[u];
    long o = g_uoff2[u];
    long ebase = (long)g_M * 67;
    int prev = -1;
    for (int i = 0; i < len; i++) {
        int v = g_vbuf[base + i];
        if (v != prev) {
            long w = ebase + 2L * o;
            if (w + 1 < out_size) {
                out[w]     = (float)u;
                out[w + 1] = (float)v;
            }
            o++; prev = v;
        }
    }
}

// ---------------- launch ----------------
extern "C" void kernel_launch(void* const* d_in, const int* in_sizes, int n_in,
                              void* d_out, int out_size) {
    const float* x     = (const float*)d_in[0];
    const float* pos   = (const float*)d_in[1];
    const int*   ei    = (const int*)d_in[2];
    const int*   batch = (const int*)d_in[3];
    float*       out   = (float*)d_out;

    const int N  = in_sizes[3];
    const int E  = in_sizes[2] / 2;
    const int ND = N * DD;
    const long osz = (long)out_size;

    const int TB = 256;
    const int gN  = (N  + TB - 1) / TB;
    const int gE  = (E  + TB - 1) / TB;
    const int gND = (ND + TB - 1) / TB;
    const int gKS = KS / TB;            // 2048
    const int gKD = KS * DD / TB;       // 131072

    k_zero1<<<gKS, TB>>>();
    k_qmax<<<gN, TB>>>(pos, N);
    k_key<<<gN, TB>>>(pos, batch, N);

    // scan flags -> rank, total -> g_M
    k_scanA<<<512, 1024>>>(0);
    k_scanB<<<1, 512>>>(0);
    k_scanC<<<gKS, TB>>>(0);

    k_ukeys<<<gKS, TB>>>();
    k_zero2<<<gKD, TB>>>();
    k_accum_pos<<<gN, TB>>>(pos, N);
    k_accum_x<<<gND, TB>>>(x, ND);

    // edge bucketing
    k_ecount<<<gE, TB>>>(ei, E);
    k_scanA<<<512, 1024>>>(1);
    k_scanB<<<1, 512>>>(1);
    k_scanC<<<gKS, TB>>>(1);
    k_escatter<<<gE, TB>>>(ei, E);
    k_sortuniq<<<gKS, TB>>>();

    // scan unique-per-u counts -> output row offsets, total -> g_Eu
    k_scanA<<<512, 1024>>>(2);
    k_scanB<<<1, 512>>>(2);
    k_scanC<<<gKS, TB>>>(2);

    k_write_main<<<gKD, TB>>>(out, osz);
    k_write_edges<<<gKS, TB>>>(out, osz);
}

// round 4
// speedup vs baseline: 1.3093x; 1.3093x over previous
#include <cuda_runtime.h>
#include <cuda_bf16.h>
#include <stdint.h>

// ---------------- static scratch (allowed: __device__ globals) ----------------
#define KS   (1 << 19)     // voxel key space upper bound: 16 * 32^3 = 524288
#define NMAX (1 << 19)     // >= N = 400000
#define EMAX (1 << 22)     // >= E = 3200000
#define DD   64
#define NEG_INF_BITS 0xFF800000u

__device__ int      g_qmax[3];
__device__ __align__(16) int g_flags[KS];
__device__ __align__(16) int g_rank[KS];
__device__ int      g_ukeys[KS];
__device__ int      g_pkey[NMAX];
__device__ int      g_pinv[NMAX];
__device__ float    g_possum[KS * 3];
__device__ int      g_pcount[KS];
__device__ __align__(16) int g_ucount[KS];
__device__ __align__(16) int g_uoff[KS];
__device__ int      g_ucursor[KS];
__device__ __align__(16) int g_ucnt2[KS];
__device__ __align__(16) int g_uoff2[KS];
__device__ int      g_vbuf[EMAX];
__device__ int      g_bsums[128];
__device__ int      g_M;
__device__ int      g_Eu;

// device-side selection of scan operands (NEVER pass __device__ symbols from host)
__device__ __forceinline__ const int* scan_in(int which) {
    return which == 0 ? g_flags : (which == 1 ? g_ucount : g_ucnt2);
}
__device__ __forceinline__ int* scan_out(int which) {
    return which == 0 ? g_rank : (which == 1 ? g_uoff : g_uoff2);
}

// ---------------- kernels ----------------

__global__ void k_zero1() {
    int i = blockIdx.x * blockDim.x + threadIdx.x;   // KS threads
    g_flags[i] = 0; g_ucount[i] = 0; g_ucursor[i] = 0; g_ucnt2[i] = 0;
    g_pcount[i] = 0;
    g_possum[3 * i + 0] = 0.0f; g_possum[3 * i + 1] = 0.0f; g_possum[3 * i + 2] = 0.0f;
    if (i < 3) g_qmax[i] = 0;
}

__global__ void k_qmax(const float* __restrict__ pos, int N) {
    __shared__ int sm[3];
    if (threadIdx.x < 3) sm[threadIdx.x] = 0;
    __syncthreads();
    int i = blockIdx.x * blockDim.x + threadIdx.x;
    if (i < N) {
#pragma unroll
        for (int j = 0; j < 3; j++) {
            int q = (int)floorf(pos[i * 3 + j] * 0.25f);
            atomicMax(&sm[j], q);
        }
    }
    __syncthreads();
    if (threadIdx.x < 3) atomicMax(&g_qmax[threadIdx.x], sm[threadIdx.x]);
}

__global__ void k_key(const float* __restrict__ pos, const int* __restrict__ batch, int N) {
    int i = blockIdx.x * blockDim.x + threadIdx.x;
    if (i >= N) return;
    int s0 = g_qmax[0] + 1, s1 = g_qmax[1] + 1, s2 = g_qmax[2] + 1;
    int q0 = (int)floorf(pos[i * 3 + 0] * 0.25f);
    int q1 = (int)floorf(pos[i * 3 + 1] * 0.25f);
    int q2 = (int)floorf(pos[i * 3 + 2] * 0.25f);
    int b  = batch[i];
    int key = ((b * s0 + q0) * s1 + q1) * s2 + q2;
    if (key < 0 || key >= KS) key = 0;   // defensive: never OOB
    g_pkey[i] = key;
    g_flags[key] = 1;
}

// --- exclusive scan over KS, 4 elems/thread: 128 blocks x 1024 threads ---
__global__ void k_scanA(int which) {
    const int4* __restrict__ in = (const int4*)scan_in(which);
    int4* __restrict__ out = (int4*)scan_out(which);
    __shared__ int ws[32];
    int t = threadIdx.x;
    int idx = blockIdx.x * 1024 + t;
    int4 a = in[idx];
    int s = a.x + a.y + a.z + a.w;
    int inc = s;
#pragma unroll
    for (int o = 1; o < 32; o <<= 1) {
        int n = __shfl_up_sync(0xffffffffu, inc, o);
        if ((t & 31) >= o) inc += n;
    }
    if ((t & 31) == 31) ws[t >> 5] = inc;
    __syncthreads();
    if (t < 32) {
        int wv = ws[t]; int winc = wv;
#pragma unroll
        for (int o = 1; o < 32; o <<= 1) {
            int n = __shfl_up_sync(0xffffffffu, winc, o);
            if (t >= o) winc += n;
        }
        ws[t] = winc - wv;
    }
    __syncthreads();
    int off = ws[t >> 5] + inc - s;      // exclusive prefix of this thread's 4 elems
    int4 r;
    r.x = off; r.y = off + a.x; r.z = r.y + a.y; r.w = r.z + a.z;
    out[idx] = r;
    if (t == 1023) g_bsums[blockIdx.x] = off + s;
}

__global__ void k_scanB(int which) {      // single block, 128 threads
    __shared__ int ws[4];
    int t = threadIdx.x;
    int v = g_bsums[t];
    int inc = v;
#pragma unroll
    for (int o = 1; o < 32; o <<= 1) {
        int n = __shfl_up_sync(0xffffffffu, inc, o);
        if ((t & 31) >= o) inc += n;
    }
    if ((t & 31) == 31) ws[t >> 5] = inc;
    __syncthreads();
    if (t < 4) {
        int wv = ws[t]; int winc = wv;
#pragma unroll
        for (int o = 1; o < 4; o <<= 1) {
            int n = __shfl_up_sync(0x0000000fu, winc, o);
            if (t >= o) winc += n;
        }
        ws[t] = winc - wv;
    }
    __syncthreads();
    int off = ws[t >> 5];
    g_bsums[t] = inc - v + off;
    if (t == 127) {
        int tot = inc + off;
        if (which == 0) g_M = tot;
        else if (which == 2) g_Eu = tot;
    }
}

__global__ void k_scanC(int which) {
    int idx = blockIdx.x * blockDim.x + threadIdx.x;   // KS/4 int4 slots
    int add = g_bsums[idx >> 10];
    int4* __restrict__ out = (int4*)scan_out(which);
    int4 r = out[idx];
    r.x += add; r.y += add; r.z += add; r.w += add;
    out[idx] = r;
    if (which == 0) {                    // fused: emit sorted unique keys
        const int4 f = ((const int4*)g_flags)[idx];
        int base = idx * 4;
        if (f.x) g_ukeys[r.x] = base;
        if (f.y) g_ukeys[r.y] = base + 1;
        if (f.z) g_ukeys[r.z] = base + 2;
        if (f.w) g_ukeys[r.w] = base + 3;
    }
}

// init out[0 .. M*64) to -inf bit pattern (16B vector stores)
__global__ void k_initout(float* __restrict__ out) {
    long idx = (long)blockIdx.x * blockDim.x + threadIdx.x;   // KS*DD/4 slots
    if (idx * 4 < (long)g_M * DD) {
        uint4 v = make_uint4(NEG_INF_BITS, NEG_INF_BITS, NEG_INF_BITS, NEG_INF_BITS);
        ((uint4*)out)[idx] = v;
    }
}

__global__ void k_accum_pos(const float* __restrict__ pos, int N) {
    int i = blockIdx.x * blockDim.x + threadIdx.x;
    if (i >= N) return;
    int inv = g_rank[g_pkey[i]];
    g_pinv[i] = inv;
    atomicAdd(&g_pcount[inv], 1);
    atomicAdd(&g_possum[inv * 3 + 0], pos[i * 3 + 0]);
    atomicAdd(&g_possum[inv * 3 + 1], pos[i * 3 + 1]);
    atomicAdd(&g_possum[inv * 3 + 2], pos[i * 3 + 2]);
}

// scatter-max of x directly into out[inv*64+d] via signbit-routed int atomics.
// init is -inf (0xFF800000). For non-negative floats (incl +0.0), int compare
// is order-preserving -> atomicMax(int). For negative floats (incl -0.0),
// uint compare is reversed -> atomicMin(uint). All mixed-sign cases resolve
// to the true float max; every segment is non-empty so -inf never leaks.
__global__ void k_accum_x(const float* __restrict__ x, float* __restrict__ out, int ND) {
    int idx = blockIdx.x * blockDim.x + threadIdx.x;   // N*64 threads
    if (idx >= ND) return;
    int i = idx >> 6, d = idx & 63;
    int inv = g_pinv[i];
    float v = x[idx];
    unsigned ub = __float_as_uint(v);
    float* addr = &out[(long)inv * DD + d];
    if (ub >> 31)
        atomicMin((unsigned*)addr, ub);
    else
        atomicMax((int*)addr, (int)ub);
}

__global__ void k_ecount(const int* __restrict__ ei, int E) {
    int e = blockIdx.x * blockDim.x + threadIdx.x;
    if (e >= E) return;
    int u = g_pinv[ei[2 * e]];
    int v = g_pinv[ei[2 * e + 1]];
    if (u != v) atomicAdd(&g_ucount[u], 1);
}

__global__ void k_escatter(const int* __restrict__ ei, int E) {
    int e = blockIdx.x * blockDim.x + threadIdx.x;
    if (e >= E) return;
    int u = g_pinv[ei[2 * e]];
    int v = g_pinv[ei[2 * e + 1]];
    if (u != v) {
        int p = g_uoff[u] + atomicAdd(&g_ucursor[u], 1);
        if (p < EMAX) g_vbuf[p] = v;
    }
}

__global__ void k_sortuniq() {
    int u = blockIdx.x * blockDim.x + threadIdx.x;    // KS threads
    if (u >= g_M) return;
    int len = g_ucount[u], base = g_uoff[u];
    for (int i = 1; i < len; i++) {                   // insertion sort (avg len ~11)
        int key = g_vbuf[base + i];
        int j = i - 1;
        while (j >= 0 && g_vbuf[base + j] > key) { g_vbuf[base + j + 1] = g_vbuf[base + j]; j--; }
        g_vbuf[base + j + 1] = key;
    }
    // compact unique values to the front of the bucket
    int c = 0;
    int prev = -1;
    for (int i = 0; i < len; i++) {
        int v = g_vbuf[base + i];
        if (v != prev) { g_vbuf[base + c] = v; c++; prev = v; }
    }
    g_ucnt2[u] = c;
}

// one thread per dedup'd output edge; bucket found by binary search on uoff2
__global__ void k_write_edges(float* __restrict__ out, long out_size) {
    int j = blockIdx.x * blockDim.x + threadIdx.x;
    if (j >= g_Eu) return;
    int lo = 0, hi = g_M;       // largest u with uoff2[u] <= j (uoff2[M] == Eu > j)
    while (hi - lo > 1) {
        int mid = (lo + hi) >> 1;
        if (g_uoff2[mid] <= j) lo = mid; else hi = mid;
    }
    int u = lo;
    int v = g_vbuf[g_uoff[u] + (j - g_uoff2[u])];
    long w = (long)g_M * 67 + 2L * j;
    if (w + 1 < out_size) {
        out[w]     = (float)u;
        out[w + 1] = (float)v;
    }
}

__global__ void k_write_main(float* __restrict__ out, long out_size) {
    long idx = (long)blockIdx.x * blockDim.x + threadIdx.x;  // KS*3 threads
    int M = g_M, Eu = g_Eu;
    if (idx < (long)M * 3) {
        long o = (long)M * DD + idx;
        if (o < out_size) out[o] = g_possum[idx] / (float)g_pcount[idx / 3];
    }
    if (idx < M) {
        long ebase = (long)M * 67;
        long s = (long)(g_qmax[0] + 1) * (g_qmax[1] + 1) * (g_qmax[2] + 1);
        long o1 = ebase + 2L * (Eu + idx);             // self loop
        long o2 = ebase + 2L * (Eu + (long)M) + idx;   // new_batch slot
        if (o1 + 1 < out_size) {
            out[o1]     = (float)idx;
            out[o1 + 1] = (float)idx;
        }
        if (o2 < out_size) out[o2] = (float)(g_ukeys[(int)idx] / (int)s);
    }
}

// ---------------- launch ----------------
extern "C" void kernel_launch(void* const* d_in, const int* in_sizes, int n_in,
                              void* d_out, int out_size) {
    const float* x     = (const float*)d_in[0];
    const float* pos   = (const float*)d_in[1];
    const int*   ei    = (const int*)d_in[2];
    const int*   batch = (const int*)d_in[3];
    float*       out   = (float*)d_out;

    const int N  = in_sizes[3];
    const int E  = in_sizes[2] / 2;
    const int ND = N * DD;
    const long osz = (long)out_size;

    const int TB = 256;
    const int gN  = (N  + TB - 1) / TB;
    const int gE  = (E  + TB - 1) / TB;
    const int gND = (ND + TB - 1) / TB;
    const int gKS = KS / TB;            // 2048

    k_zero1<<<gKS, TB>>>();
    k_qmax<<<gN, TB>>>(pos, N);
    k_key<<<gN, TB>>>(pos, batch, N);

    // scan flags -> rank (+ukeys fused), total -> g_M
    k_scanA<<<128, 1024>>>(0);
    k_scanB<<<1, 128>>>(0);
    k_scanC<<<512, 256>>>(0);

    k_initout<<<KS * DD / 4 / TB, TB>>>(out);
    k_accum_pos<<<gN, TB>>>(pos, N);
    k_accum_x<<<gND, TB>>>(x, out, ND);

    // edge bucketing
    k_ecount<<<gE, TB>>>(ei, E);
    k_scanA<<<128, 1024>>>(1);
    k_scanB<<<1, 128>>>(1);
    k_scanC<<<512, 256>>>(1);
    k_escatter<<<gE, TB>>>(ei, E);
    k_sortuniq<<<gKS, TB>>>();

    // scan unique-per-u counts -> output row offsets, total -> g_Eu
    k_scanA<<<128, 1024>>>(2);
    k_scanB<<<1, 128>>>(2);
    k_scanC<<<512, 256>>>(2);

    k_write_edges<<<EMAX / TB, TB>>>(out, osz);
    k_write_main<<<3 * gKS, TB>>>(out, osz);
}

// round 5
// speedup vs baseline: 1.3881x; 1.0602x over previous
#include <cuda_runtime.h>
#include <cuda_bf16.h>
#include <stdint.h>

// ---------------- static scratch ----------------
#define KS   (1 << 19)     // key space: 16 batches * 32^3 voxels = 524288
#define NMAX (1 << 19)
#define EMAX (1 << 22)
#define DD   64
#define NEG_INF __int_as_float(0xFF800000)

__device__ __align__(16) int g_flags[KS];
__device__ __align__(16) int g_rank[KS];
__device__ int      g_ukeys[KS];
__device__ int      g_pkey[NMAX];
__device__ int      g_pinv[NMAX];
__device__ int      g_order[NMAX];
__device__ float    g_possum[KS * 3];
__device__ __align__(16) int g_pcount[KS];
__device__ __align__(16) int g_poff[KS];
__device__ int      g_pcursor[KS];
__device__ __align__(16) int g_ucount[KS];
__device__ __align__(16) int g_uoff[KS];
__device__ int      g_ucursor[KS];
__device__ __align__(16) int g_ucnt2[KS];
__device__ __align__(16) int g_uoff2[KS];
__device__ int      g_vbuf[EMAX];
__device__ unsigned long long g_status[4][128];   // decoupled-lookback state
__device__ int      g_M;
__device__ int      g_Eu;

__device__ __forceinline__ const int* scan_in(int w) {
    return w == 0 ? g_flags : (w == 1 ? g_ucount : (w == 2 ? g_ucnt2 : g_pcount));
}
__device__ __forceinline__ int* scan_out(int w) {
    return w == 0 ? g_rank : (w == 1 ? g_uoff : (w == 2 ? g_uoff2 : g_poff));
}

// ---------------- kernels ----------------

__global__ void k_zero() {
    int i = blockIdx.x * blockDim.x + threadIdx.x;   // KS/4 int4 slots
    int4 z = make_int4(0, 0, 0, 0);
    ((int4*)g_flags)[i] = z; ((int4*)g_ucount)[i] = z; ((int4*)g_ucursor)[i] = z;
    ((int4*)g_ucnt2)[i] = z; ((int4*)g_pcount)[i] = z; ((int4*)g_pcursor)[i] = z;
    ((float4*)g_possum)[i] = make_float4(0.f, 0.f, 0.f, 0.f);
    ((float4*)g_possum)[i + KS / 4] = make_float4(0.f, 0.f, 0.f, 0.f);
    ((float4*)g_possum)[i + KS / 2] = make_float4(0.f, 0.f, 0.f, 0.f);
    if (i < 4 * 128) ((unsigned long long*)g_status)[i] = 0ULL;
}

// fixed strides (pos < 128 => q in [0,31]): key order == reference lexicographic order
__global__ void k_key(const float* __restrict__ pos, const int* __restrict__ batch, int N) {
    int i = blockIdx.x * blockDim.x + threadIdx.x;
    if (i >= N) return;
    int q0 = (int)floorf(pos[i * 3 + 0] * 0.25f);
    int q1 = (int)floorf(pos[i * 3 + 1] * 0.25f);
    int q2 = (int)floorf(pos[i * 3 + 2] * 0.25f);
    int key = (batch[i] << 15) | (q0 << 10) | (q1 << 5) | q2;
    if (key < 0 || key >= KS) key = 0;
    g_pkey[i] = key;
    g_flags[key] = 1;
}

// single-pass decoupled-lookback exclusive scan: 128 blocks x 1024 threads x int4
__global__ void k_scan(int which) {
    const int4* __restrict__ in = (const int4*)scan_in(which);
    int4* __restrict__ out = (int4*)scan_out(which);
    unsigned long long* st = g_status[which];
    __shared__ int ws[32];
    __shared__ int s_exc;
    int t = threadIdx.x, b = blockIdx.x;
    int4 a = in[b * 1024 + t];
    int s = a.x + a.y + a.z + a.w;
    int inc = s;
#pragma unroll
    for (int o = 1; o < 32; o <<= 1) {
        int n = __shfl_up_sync(0xffffffffu, inc, o);
        if ((t & 31) >= o) inc += n;
    }
    if ((t & 31) == 31) ws[t >> 5] = inc;
    __syncthreads();
    if (t < 32) {
        int wv = ws[t]; int winc = wv;
#pragma unroll
        for (int o = 1; o < 32; o <<= 1) {
            int n = __shfl_up_sync(0xffffffffu, winc, o);
            if (t >= o) winc += n;
        }
        ws[t] = winc - wv;
    }
    __syncthreads();
    inc += ws[t >> 5];                       // block-inclusive prefix of s
    // publish aggregate (block 0 publishes its inclusive directly)
    if (t == 1023) {
        unsigned long long flag = (b == 0) ? 2ULL : 1ULL;
        *(volatile unsigned long long*)&st[b] = (flag << 32) | (unsigned)inc;
    }
    // lookback
    if (t == 0) {
        int exc = 0;
        if (b > 0) {
            int j = b - 1;
            while (true) {
                unsigned long long v;
                do { v = *(volatile unsigned long long*)&st[j]; } while ((v >> 32) == 0ULL);
                exc += (int)(unsigned)v;
                if ((v >> 32) == 2ULL) break;
                j--;
            }
        }
        s_exc = exc;
    }
    __syncthreads();
    int exc = s_exc;
    if (t == 1023) {
        if (b > 0)
            *(volatile unsigned long long*)&st[b] = (2ULL << 32) | (unsigned)(exc + inc);
        if (b == 127) {
            int tot = exc + inc;
            if (which == 0) g_M = tot;
            else if (which == 2) g_Eu = tot;
        }
    }
    int base = exc + inc - s;                // exclusive prefix of this thread's 4 elems
    int4 r;
    r.x = base; r.y = base + a.x; r.z = r.y + a.y; r.w = r.z + a.z;
    out[b * 1024 + t] = r;
    if (which == 0) {                        // fused: emit sorted unique keys
        int kbase = (b * 1024 + t) * 4;
        if (a.x) g_ukeys[r.x] = kbase;
        if (a.y) g_ukeys[r.y] = kbase + 1;
        if (a.z) g_ukeys[r.z] = kbase + 2;
        if (a.w) g_ukeys[r.w] = kbase + 3;
    }
}

__global__ void k_accum_pos(const float* __restrict__ pos, int N) {
    int i = blockIdx.x * blockDim.x + threadIdx.x;
    if (i >= N) return;
    int inv = g_rank[g_pkey[i]];
    g_pinv[i] = inv;
    atomicAdd(&g_pcount[inv], 1);
    atomicAdd(&g_possum[inv * 3 + 0], pos[i * 3 + 0]);
    atomicAdd(&g_possum[inv * 3 + 1], pos[i * 3 + 1]);
    atomicAdd(&g_possum[inv * 3 + 2], pos[i * 3 + 2]);
}

__global__ void k_porder(int N) {
    int i = blockIdx.x * blockDim.x + threadIdx.x;
    if (i >= N) return;
    int inv = g_pinv[i];
    int p = g_poff[inv] + atomicAdd(&g_pcursor[inv], 1);
    if (p >= 0 && p < NMAX) g_order[p] = i;
}

// gather-max: thread = (voxel, 4-dim group). Coalesced float4 reads of x rows,
// single coalesced write to out. No init, no atomics.
__global__ void k_gather_x(const float* __restrict__ x, float* __restrict__ out) {
    int idx = blockIdx.x * blockDim.x + threadIdx.x;   // KS*16 threads
    int voxel = idx >> 4, dq = idx & 15;
    if (voxel >= g_M) return;
    int off = g_poff[voxel], cnt = g_pcount[voxel];
    float4 m = make_float4(NEG_INF, NEG_INF, NEG_INF, NEG_INF);
    for (int j = 0; j < cnt; j++) {
        int p = g_order[off + j];
        float4 v = ((const float4*)x)[p * 16 + dq];
        m.x = fmaxf(m.x, v.x); m.y = fmaxf(m.y, v.y);
        m.z = fmaxf(m.z, v.z); m.w = fmaxf(m.w, v.w);
    }
    ((float4*)out)[voxel * 16 + dq] = m;
}

__global__ void k_ecount(const int* __restrict__ ei, int E) {
    int e = blockIdx.x * blockDim.x + threadIdx.x;
    if (e >= E) return;
    int2 uv = ((const int2*)ei)[e];
    int u = g_pinv[uv.x], v = g_pinv[uv.y];
    if (u != v) atomicAdd(&g_ucount[u], 1);
}

__global__ void k_escatter(const int* __restrict__ ei, int E) {
    int e = blockIdx.x * blockDim.x + threadIdx.x;
    if (e >= E) return;
    int2 uv = ((const int2*)ei)[e];
    int u = g_pinv[uv.x], v = g_pinv[uv.y];
    if (u != v) {
        int p = g_uoff[u] + atomicAdd(&g_ucursor[u], 1);
        if (p < EMAX) g_vbuf[p] = v;
    }
}

__global__ void k_sortuniq() {
    int u = blockIdx.x * blockDim.x + threadIdx.x;    // KS threads
    if (u >= g_M) return;
    int len = g_ucount[u], base = g_uoff[u];
    for (int i = 1; i < len; i++) {                   // insertion sort (avg len ~11)
        int key = g_vbuf[base + i];
        int j = i - 1;
        while (j >= 0 && g_vbuf[base + j] > key) { g_vbuf[base + j + 1] = g_vbuf[base + j]; j--; }
        g_vbuf[base + j + 1] = key;
    }
    int c = 0, prev = -1;                             // compact unique to front
    for (int i = 0; i < len; i++) {
        int v = g_vbuf[base + i];
        if (v != prev) { g_vbuf[base + c] = v; c++; prev = v; }
    }
    g_ucnt2[u] = c;
}

// one thread per dedup'd edge; bucket via binary search on uoff2 (L2-resident)
__global__ void k_write_edges(float* __restrict__ out, long out_size) {
    int j = blockIdx.x * blockDim.x + threadIdx.x;
    if (j >= g_Eu) return;
    int lo = 0, hi = g_M;
    while (hi - lo > 1) {
        int mid = (lo + hi) >> 1;
        if (g_uoff2[mid] <= j) lo = mid; else hi = mid;
    }
    int u = lo;
    int v = g_vbuf[g_uoff[u] + (j - g_uoff2[u])];
    long w = (long)g_M * 67 + 2L * j;
    if (w + 1 < out_size) { out[w] = (float)u; out[w + 1] = (float)v; }
}

__global__ void k_write_main(float* __restrict__ out, long out_size) {
    long idx = (long)blockIdx.x * blockDim.x + threadIdx.x;  // KS*3 threads
    int M = g_M, Eu = g_Eu;
    if (idx < (long)M * 3) {
        long o = (long)M * DD + idx;
        if (o < out_size) out[o] = g_possum[idx] / (float)g_pcount[idx / 3];
    }
    if (idx < M) {
        long ebase = (long)M * 67;
        long o1 = ebase + 2L * (Eu + idx);             // self loop
        long o2 = ebase + 2L * (Eu + (long)M) + idx;   // new_batch slot
        if (o1 + 1 < out_size) { out[o1] = (float)idx; out[o1 + 1] = (float)idx; }
        if (o2 < out_size) out[o2] = (float)(g_ukeys[(int)idx] >> 15);
    }
}

// ---------------- launch ----------------
extern "C" void kernel_launch(void* const* d_in, const int* in_sizes, int n_in,
                              void* d_out, int out_size) {
    const float* x     = (const float*)d_in[0];
    const float* pos   = (const float*)d_in[1];
    const int*   ei    = (const int*)d_in[2];
    const int*   batch = (const int*)d_in[3];
    float*       out   = (float*)d_out;

    const int N = in_sizes[3];
    const int E = in_sizes[2] / 2;
    const long osz = (long)out_size;

    const int TB = 256;
    const int gN = (N + TB - 1) / TB;
    const int gE = (E + TB - 1) / TB;

    k_zero<<<KS / 4 / TB, TB>>>();
    k_key<<<gN, TB>>>(pos, batch, N);
    k_scan<<<128, 1024>>>(0);                 // flags -> rank (+ukeys), g_M

    k_accum_pos<<<gN, TB>>>(pos, N);
    k_scan<<<128, 1024>>>(3);                 // pcount -> poff
    k_porder<<<gN, TB>>>(N);
    k_gather_x<<<KS * 16 / TB, TB>>>(x, out);

    k_ecount<<<gE, TB>>>(ei, E);
    k_scan<<<128, 1024>>>(1);                 // ucount -> uoff
    k_escatter<<<gE, TB>>>(ei, E);
    k_sortuniq<<<KS / TB, TB>>>();
    k_scan<<<128, 1024>>>(2);                 // ucnt2 -> uoff2, g_Eu

    k_write_edges<<<EMAX / TB, TB>>>(out, osz);
    k_write_main<<<3 * KS / TB, TB>>>(out, osz);
}

// round 7
// speedup vs baseline: 1.4375x; 1.0356x over previous
#include <cuda_runtime.h>
#include <cuda_bf16.h>
#include <stdint.h>

// ---------------- static scratch ----------------
#define KS   (1 << 19)     // key space: 16 batches * 32^3 voxels
#define NMAX (1 << 19)
#define EMAX (1 << 22)
#define DD   64
#define NEG_INF __int_as_float(0xFF800000)
typedef unsigned long long ull;

#define M24 0xFFFFFFull
#define VMASK ((1ull << 48) - 1ull)

__device__ __align__(16) int g_pcount[KS];   // per-KEY point count
__device__ __align__(16) int g_poff[KS];     // per-KEY counting-sort offset
__device__ __align__(16) int g_rank[KS];     // per-KEY unique rank
__device__ int      g_ukeys[KS];
__device__ int      g_pkey[NMAX];
__device__ int      g_pinv[NMAX];
__device__ int      g_order[NMAX];
__device__ int      g_pcursor[KS];
__device__ __align__(16) int g_ucount[KS];
__device__ __align__(16) int g_uoff[KS];
__device__ int      g_ucursor[KS];
__device__ __align__(16) int g_ucnt2[KS];
__device__ __align__(16) int g_uoff2[KS];
__device__ int      g_vbuf[EMAX];
__device__ ull      g_euv[EMAX];
__device__ ull      g_st0[128];              // packed status: count|rank|flag
__device__ ull      g_st[2][128];            // packed status: (flag<<32)|value
__device__ int      g_M;
__device__ int      g_Eu;

__device__ __forceinline__ const int* scan_in(int w)  { return w == 0 ? g_ucount : g_ucnt2; }
__device__ __forceinline__ int*       scan_out(int w) { return w == 0 ? g_uoff   : g_uoff2; }

// ---------------- kernels ----------------

__global__ void k_zero() {
    int i = blockIdx.x * blockDim.x + threadIdx.x;   // KS/4 int4 slots
    int4 z = make_int4(0, 0, 0, 0);
    ((int4*)g_pcount)[i] = z; ((int4*)g_pcursor)[i] = z;
    ((int4*)g_ucount)[i] = z; ((int4*)g_ucursor)[i] = z; ((int4*)g_ucnt2)[i] = z;
    if (i < 128) { g_st0[i] = 0ULL; g_st[0][i] = 0ULL; g_st[1][i] = 0ULL; }
}

// fixed strides (pos in [0,128) => q in [0,31]): key order == reference order
__global__ void k_key(const float* __restrict__ pos, const int* __restrict__ batch, int N) {
    int i = blockIdx.x * blockDim.x + threadIdx.x;
    if (i >= N) return;
    int q0 = (int)floorf(pos[i * 3 + 0] * 0.25f);
    int q1 = (int)floorf(pos[i * 3 + 1] * 0.25f);
    int q2 = (int)floorf(pos[i * 3 + 2] * 0.25f);
    int key = (batch[i] << 15) | (q0 << 10) | (q1 << 5) | q2;
    if (key < 0 || key >= KS) key = 0;
    g_pkey[i] = key;
    atomicAdd(&g_pcount[key], 1);
}

// decoupled-lookback scan over g_pcount, dual payload packed in one 64-bit word:
// bits[0:24)=count prefix (poff), bits[24:48)=indicator prefix (rank), bits[62:64)=flag.
// Single volatile 64-bit publish => no flag/value race (the R6 bug).
__global__ void k_scan0() {
    const int4* __restrict__ in = (const int4*)g_pcount;
    __shared__ ull ws[32];
    __shared__ ull s_exc;
    int t = threadIdx.x, b = blockIdx.x;
    int4 a = in[b * 1024 + t];
    ull px = (ull)(unsigned)a.x + ((ull)(a.x > 0) << 24);
    ull py = (ull)(unsigned)a.y + ((ull)(a.y > 0) << 24);
    ull pz = (ull)(unsigned)a.z + ((ull)(a.z > 0) << 24);
    ull pw = (ull)(unsigned)a.w + ((ull)(a.w > 0) << 24);
    ull s = px + py + pz + pw;
    ull inc = s;
#pragma unroll
    for (int o = 1; o < 32; o <<= 1) {
        ull n = __shfl_up_sync(0xffffffffu, inc, o);
        if ((t & 31) >= o) inc += n;
    }
    if ((t & 31) == 31) ws[t >> 5] = inc;
    __syncthreads();
    if (t < 32) {
        ull wv = ws[t]; ull winc = wv;
#pragma unroll
        for (int o = 1; o < 32; o <<= 1) {
            ull n = __shfl_up_sync(0xffffffffu, winc, o);
            if (t >= o) winc += n;
        }
        ws[t] = winc - wv;
    }
    __syncthreads();
    inc += ws[t >> 5];                       // block-inclusive packed prefix
    if (t == 1023)
        *(volatile ull*)&g_st0[b] = inc | ((b == 0 ? 2ULL : 1ULL) << 62);
    if (t == 0) {
        ull exc = 0;
        if (b > 0) {
            int j = b - 1;
            while (true) {
                ull v;
                do { v = *(volatile ull*)&g_st0[j]; } while ((v >> 62) == 0ULL);
                exc += v & VMASK;
                if ((v >> 62) == 2ULL) break;
                j--;
            }
        }
        s_exc = exc;
    }
    __syncthreads();
    ull exc = s_exc;
    if (t == 1023) {
        if (b > 0)
            *(volatile ull*)&g_st0[b] = ((exc + inc) & VMASK) | (2ULL << 62);
        if (b == 127) g_M = (int)(((exc + inc) >> 24) & M24);
    }
    ull base = exc + inc - s;
    ull r0 = base, r1 = base + px, r2 = r1 + py, r3 = r2 + pz;
    int idx = b * 1024 + t;
    int4 off  = make_int4((int)(r0 & M24), (int)(r1 & M24), (int)(r2 & M24), (int)(r3 & M24));
    int4 rank = make_int4((int)((r0 >> 24) & M24), (int)((r1 >> 24) & M24),
                          (int)((r2 >> 24) & M24), (int)((r3 >> 24) & M24));
    ((int4*)g_poff)[idx] = off;
    ((int4*)g_rank)[idx] = rank;
    int kbase = idx * 4;
    if (a.x) g_ukeys[rank.x] = kbase;
    if (a.y) g_ukeys[rank.y] = kbase + 1;
    if (a.z) g_ukeys[rank.z] = kbase + 2;
    if (a.w) g_ukeys[rank.w] = kbase + 3;
}

// 32-bit lookback scan, packed (flag<<32)|value status (R5-proven format)
__global__ void k_scan(int which) {
    const int4* __restrict__ in = (const int4*)scan_in(which);
    int4* __restrict__ out = (int4*)scan_out(which);
    ull* st = g_st[which];
    __shared__ int ws[32];
    __shared__ int s_exc;
    int t = threadIdx.x, b = blockIdx.x;
    int4 a = in[b * 1024 + t];
    int s = a.x + a.y + a.z + a.w;
    int inc = s;
#pragma unroll
    for (int o = 1; o < 32; o <<= 1) {
        int n = __shfl_up_sync(0xffffffffu, inc, o);
        if ((t & 31) >= o) inc += n;
    }
    if ((t & 31) == 31) ws[t >> 5] = inc;
    __syncthreads();
    if (t < 32) {
        int wv = ws[t]; int winc = wv;
#pragma unroll
        for (int o = 1; o < 32; o <<= 1) {
            int n = __shfl_up_sync(0xffffffffu, winc, o);
            if (t >= o) winc += n;
        }
        ws[t] = winc - wv;
    }
    __syncthreads();
    inc += ws[t >> 5];
    if (t == 1023)
        *(volatile ull*)&st[b] = ((b == 0 ? 2ULL : 1ULL) << 32) | (unsigned)inc;
    if (t == 0) {
        int exc = 0;
        if (b > 0) {
            int j = b - 1;
            while (true) {
                ull v;
                do { v = *(volatile ull*)&st[j]; } while ((v >> 32) == 0ULL);
                exc += (int)(unsigned)v;
                if ((v >> 32) == 2ULL) break;
                j--;
            }
        }
        s_exc = exc;
    }
    __syncthreads();
    int exc = s_exc;
    if (t == 1023) {
        if (b > 0)
            *(volatile ull*)&st[b] = (2ULL << 32) | (unsigned)(exc + inc);
        if (b == 127 && which == 1) g_Eu = exc + inc;
    }
    int base = exc + inc - s;
    int4 r;
    r.x = base; r.y = base + a.x; r.z = r.y + a.y; r.w = r.z + a.z;
    out[b * 1024 + t] = r;
}

__global__ void k_porder(int N) {
    int i = blockIdx.x * blockDim.x + threadIdx.x;
    if (i >= N) return;
    int key = g_pkey[i];
    int p = g_poff[key] + atomicAdd(&g_pcursor[key], 1);
    if (p >= 0 && p < NMAX) g_order[p] = i;
    g_pinv[i] = g_rank[key];
}

// gather-max: thread = (voxel, 4-dim group); coalesced float4 row reads, one write
__global__ void k_gather_x(const float* __restrict__ x, float* __restrict__ out) {
    int idx = blockIdx.x * blockDim.x + threadIdx.x;   // KS*16 threads
    int voxel = idx >> 4, dq = idx & 15;
    if (voxel >= g_M) return;
    int ukey = g_ukeys[voxel];
    int off = g_poff[ukey], cnt = g_pcount[ukey];
    float4 m = make_float4(NEG_INF, NEG_INF, NEG_INF, NEG_INF);
    for (int j = 0; j < cnt; j++) {
        int p = g_order[off + j];
        float4 v = ((const float4*)x)[p * 16 + dq];
        m.x = fmaxf(m.x, v.x); m.y = fmaxf(m.y, v.y);
        m.z = fmaxf(m.z, v.z); m.w = fmaxf(m.w, v.w);
    }
    ((float4*)out)[voxel * 16 + dq] = m;
}

// gather pos mean: thread = voxel
__global__ void k_gather_pos(const float* __restrict__ pos, float* __restrict__ out, long out_size) {
    int voxel = blockIdx.x * blockDim.x + threadIdx.x;
    if (voxel >= g_M) return;
    int ukey = g_ukeys[voxel];
    int off = g_poff[ukey], cnt = g_pcount[ukey];
    float s0 = 0.f, s1 = 0.f, s2 = 0.f;
    for (int j = 0; j < cnt; j++) {
        int p = g_order[off + j];
        s0 += pos[p * 3 + 0]; s1 += pos[p * 3 + 1]; s2 += pos[p * 3 + 2];
    }
    float inv = 1.0f / (float)cnt;
    long o = (long)g_M * DD + (long)voxel * 3;
    if (o + 2 < out_size) { out[o] = s0 * inv; out[o + 1] = s1 * inv; out[o + 2] = s2 * inv; }
}

// gather pinv once; pack (u,v) for reuse by escatter
__global__ void k_ecount(const int* __restrict__ ei, int E) {
    int e = blockIdx.x * blockDim.x + threadIdx.x;
    if (e >= E) return;
    int2 uv = ((const int2*)ei)[e];
    int u = g_pinv[uv.x], v = g_pinv[uv.y];
    g_euv[e] = ((ull)(unsigned)u << 32) | (unsigned)v;
    if (u != v) atomicAdd(&g_ucount[u], 1);
}

__global__ void k_escatter(int E) {
    int e = blockIdx.x * blockDim.x + threadIdx.x;
    if (e >= E) return;
    ull w = g_euv[e];
    int u = (int)(w >> 32), v = (int)(unsigned)w;
    if (u != v) {
        int p = g_uoff[u] + atomicAdd(&g_ucursor[u], 1);
        if (p < EMAX) g_vbuf[p] = v;
    }
}

__global__ void k_sortuniq() {
    int u = blockIdx.x * blockDim.x + threadIdx.x;    // KS threads
    if (u >= g_M) return;
    int len = g_ucount[u], base = g_uoff[u];
    for (int i = 1; i < len; i++) {
        int key = g_vbuf[base + i];
        int j = i - 1;
        while (j >= 0 && g_vbuf[base + j] > key) { g_vbuf[base + j + 1] = g_vbuf[base + j]; j--; }
        g_vbuf[base + j + 1] = key;
    }
    int c = 0, prev = -1;
    for (int i = 0; i < len; i++) {
        int v = g_vbuf[base + i];
        if (v != prev) { g_vbuf[base + c] = v; c++; prev = v; }
    }
    g_ucnt2[u] = c;
}

// warp per voxel: lanes stride over dedup'd v's (c may exceed 32)
__global__ void k_write_edges(float* __restrict__ out, long out_size) {
    int gw = (blockIdx.x * blockDim.x + threadIdx.x) >> 5;   // global warp id = voxel
    int lane = threadIdx.x & 31;
    if (gw >= g_M) return;
    int c = g_ucnt2[gw];
    int base = g_uoff[gw];
    long wbase = (long)g_M * 67 + 2L * g_uoff2[gw];
    for (int i = lane; i < c; i += 32) {
        int v = g_vbuf[base + i];
        long w = wbase + 2L * i;
        if (w + 1 < out_size) { out[w] = (float)gw; out[w + 1] = (float)v; }
    }
}

__global__ void k_write_tail(float* __restrict__ out, long out_size) {
    int voxel = blockIdx.x * blockDim.x + threadIdx.x;
    int M = g_M, Eu = g_Eu;
    if (voxel >= M) return;
    long ebase = (long)M * 67;
    long o1 = ebase + 2L * (Eu + voxel);
    long o2 = ebase + 2L * (Eu + (long)M) + voxel;
    if (o1 + 1 < out_size) { out[o1] = (float)voxel; out[o1 + 1] = (float)voxel; }
    if (o2 < out_size) out[o2] = (float)(g_ukeys[voxel] >> 15);
}

// ---------------- launch ----------------
extern "C" void kernel_launch(void* const* d_in, const int* in_sizes, int n_in,
                              void* d_out, int out_size) {
    const float* x     = (const float*)d_in[0];
    const float* pos   = (const float*)d_in[1];
    const int*   ei    = (const int*)d_in[2];
    const int*   batch = (const int*)d_in[3];
    float*       out   = (float*)d_out;

    const int N = in_sizes[3];
    const int E = in_sizes[2] / 2;
    const long osz = (long)out_size;

    const int TB = 256;
    const int gN = (N + TB - 1) / TB;
    const int gE = (E + TB - 1) / TB;

    k_zero<<<KS / 4 / TB, TB>>>();
    k_key<<<gN, TB>>>(pos, batch, N);
    k_scan0<<<128, 1024>>>();                    // pcount -> poff + rank + ukeys + M
    k_porder<<<gN, TB>>>(N);                     // order + pinv

    k_gather_x<<<KS * 16 / TB, TB>>>(x, out);
    k_gather_pos<<<KS / TB, TB>>>(pos, out, osz);

    k_ecount<<<gE, TB>>>(ei, E);                 // pinv gather once; pack euv
    k_scan<<<128, 1024>>>(0);                    // ucount -> uoff
    k_escatter<<<gE, TB>>>(E);
    k_sortuniq<<<KS / TB, TB>>>();
    k_scan<<<128, 1024>>>(1);                    // ucnt2 -> uoff2 + Eu

    k_write_edges<<<KS * 32 / TB, TB>>>(out, osz);
    k_write_tail<<<KS / TB, TB>>>(out, osz);
}

// round 8
// speedup vs baseline: 1.4624x; 1.0173x over previous
#include <cuda_runtime.h>
#include <cuda_bf16.h>
#include <stdint.h>

// ---------------- static scratch ----------------
#define KS   (1 << 19)     // key space: 16 batches * 32^3 voxels
#define NMAX (1 << 19)
#define EMAX (1 << 22)
#define DD   64
#define NEG_INF __int_as_float(0xFF800000)
typedef unsigned long long ull;

#define M24 0xFFFFFFull
#define VMASK ((1ull << 48) - 1ull)

__device__ __align__(16) int g_pcount[KS];
__device__ __align__(16) int g_poff[KS];
__device__ __align__(16) int g_rank[KS];
__device__ int      g_ukeys[KS];
__device__ int      g_pkey[NMAX];
__device__ int      g_pinv[NMAX];
__device__ int      g_order[NMAX];
__device__ int      g_pcursor[KS];
__device__ __align__(16) int g_ucount[KS];
__device__ __align__(16) int g_uoff[KS];
__device__ int      g_ucursor[KS];
__device__ __align__(16) int g_ucnt2[KS];
__device__ __align__(16) int g_uoff2[KS];
__device__ int      g_vbuf[EMAX];
__device__ ull      g_euv[EMAX];
__device__ ull      g_st0[128];
__device__ ull      g_st[2][128];
__device__ int      g_M;
__device__ int      g_Eu;

__device__ __forceinline__ const int* scan_in(int w)  { return w == 0 ? g_ucount : g_ucnt2; }
__device__ __forceinline__ int*       scan_out(int w) { return w == 0 ? g_uoff   : g_uoff2; }

// ---------------- kernels ----------------

__global__ void k_zero() {
    int i = blockIdx.x * blockDim.x + threadIdx.x;   // KS/4 int4 slots
    int4 z = make_int4(0, 0, 0, 0);
    ((int4*)g_pcount)[i] = z; ((int4*)g_pcursor)[i] = z;
    ((int4*)g_ucount)[i] = z; ((int4*)g_ucursor)[i] = z; ((int4*)g_ucnt2)[i] = z;
    if (i < 128) { g_st0[i] = 0ULL; g_st[0][i] = 0ULL; g_st[1][i] = 0ULL; }
}

__global__ void k_key(const float* __restrict__ pos, const int* __restrict__ batch, int N) {
    int i = blockIdx.x * blockDim.x + threadIdx.x;
    if (i >= N) return;
    int q0 = (int)floorf(pos[i * 3 + 0] * 0.25f);
    int q1 = (int)floorf(pos[i * 3 + 1] * 0.25f);
    int q2 = (int)floorf(pos[i * 3 + 2] * 0.25f);
    int key = (batch[i] << 15) | (q0 << 10) | (q1 << 5) | q2;
    if (key < 0 || key >= KS) key = 0;
    g_pkey[i] = key;
    atomicAdd(&g_pcount[key], 1);
}

// dual-payload lookback scan: bits[0:24)=count prefix, [24:48)=indicator prefix, [62:64)=flag
__global__ void k_scan0() {
    const int4* __restrict__ in = (const int4*)g_pcount;
    __shared__ ull ws[32];
    __shared__ ull s_exc;
    int t = threadIdx.x, b = blockIdx.x;
    int4 a = in[b * 1024 + t];
    ull px = (ull)(unsigned)a.x + ((ull)(a.x > 0) << 24);
    ull py = (ull)(unsigned)a.y + ((ull)(a.y > 0) << 24);
    ull pz = (ull)(unsigned)a.z + ((ull)(a.z > 0) << 24);
    ull pw = (ull)(unsigned)a.w + ((ull)(a.w > 0) << 24);
    ull s = px + py + pz + pw;
    ull inc = s;
#pragma unroll
    for (int o = 1; o < 32; o <<= 1) {
        ull n = __shfl_up_sync(0xffffffffu, inc, o);
        if ((t & 31) >= o) inc += n;
    }
    if ((t & 31) == 31) ws[t >> 5] = inc;
    __syncthreads();
    if (t < 32) {
        ull wv = ws[t]; ull winc = wv;
#pragma unroll
        for (int o = 1; o < 32; o <<= 1) {
            ull n = __shfl_up_sync(0xffffffffu, winc, o);
            if (t >= o) winc += n;
        }
        ws[t] = winc - wv;
    }
    __syncthreads();
    inc += ws[t >> 5];
    if (t == 1023)
        *(volatile ull*)&g_st0[b] = inc | ((b == 0 ? 2ULL : 1ULL) << 62);
    if (t == 0) {
        ull exc = 0;
        if (b > 0) {
            int j = b - 1;
            while (true) {
                ull v;
                do { v = *(volatile ull*)&g_st0[j]; } while ((v >> 62) == 0ULL);
                exc += v & VMASK;
                if ((v >> 62) == 2ULL) break;
                j--;
            }
        }
        s_exc = exc;
    }
    __syncthreads();
    ull exc = s_exc;
    if (t == 1023) {
        if (b > 0)
            *(volatile ull*)&g_st0[b] = ((exc + inc) & VMASK) | (2ULL << 62);
        if (b == 127) g_M = (int)(((exc + inc) >> 24) & M24);
    }
    ull base = exc + inc - s;
    ull r0 = base, r1 = base + px, r2 = r1 + py, r3 = r2 + pz;
    int idx = b * 1024 + t;
    int4 off  = make_int4((int)(r0 & M24), (int)(r1 & M24), (int)(r2 & M24), (int)(r3 & M24));
    int4 rank = make_int4((int)((r0 >> 24) & M24), (int)((r1 >> 24) & M24),
                          (int)((r2 >> 24) & M24), (int)((r3 >> 24) & M24));
    ((int4*)g_poff)[idx] = off;
    ((int4*)g_rank)[idx] = rank;
    int kbase = idx * 4;
    if (a.x) g_ukeys[rank.x] = kbase;
    if (a.y) g_ukeys[rank.y] = kbase + 1;
    if (a.z) g_ukeys[rank.z] = kbase + 2;
    if (a.w) g_ukeys[rank.w] = kbase + 3;
}

// 32-bit lookback scan, packed (flag<<32)|value status
__global__ void k_scan(int which) {
    const int4* __restrict__ in = (const int4*)scan_in(which);
    int4* __restrict__ out = (int4*)scan_out(which);
    ull* st = g_st[which];
    __shared__ int ws[32];
    __shared__ int s_exc;
    int t = threadIdx.x, b = blockIdx.x;
    int4 a = in[b * 1024 + t];
    int s = a.x + a.y + a.z + a.w;
    int inc = s;
#pragma unroll
    for (int o = 1; o < 32; o <<= 1) {
        int n = __shfl_up_sync(0xffffffffu, inc, o);
        if ((t & 31) >= o) inc += n;
    }
    if ((t & 31) == 31) ws[t >> 5] = inc;
    __syncthreads();
    if (t < 32) {
        int wv = ws[t]; int winc = wv;
#pragma unroll
        for (int o = 1; o < 32; o <<= 1) {
            int n = __shfl_up_sync(0xffffffffu, winc, o);
            if (t >= o) winc += n;
        }
        ws[t] = winc - wv;
    }
    __syncthreads();
    inc += ws[t >> 5];
    if (t == 1023)
        *(volatile ull*)&st[b] = ((b == 0 ? 2ULL : 1ULL) << 32) | (unsigned)inc;
    if (t == 0) {
        int exc = 0;
        if (b > 0) {
            int j = b - 1;
            while (true) {
                ull v;
                do { v = *(volatile ull*)&st[j]; } while ((v >> 32) == 0ULL);
                exc += (int)(unsigned)v;
                if ((v >> 32) == 2ULL) break;
                j--;
            }
        }
        s_exc = exc;
    }
    __syncthreads();
    int exc = s_exc;
    if (t == 1023) {
        if (b > 0)
            *(volatile ull*)&st[b] = (2ULL << 32) | (unsigned)(exc + inc);
        if (b == 127 && which == 1) g_Eu = exc + inc;
    }
    int base = exc + inc - s;
    int4 r;
    r.x = base; r.y = base + a.x; r.z = r.y + a.y; r.w = r.z + a.z;
    out[b * 1024 + t] = r;
}

__global__ void k_porder(int N) {
    int i = blockIdx.x * blockDim.x + threadIdx.x;
    if (i >= N) return;
    int key = g_pkey[i];
    int p = g_poff[key] + atomicAdd(&g_pcursor[key], 1);
    if (p >= 0 && p < NMAX) g_order[p] = i;
    g_pinv[i] = g_rank[key];
}

__global__ void k_gather_x(const float* __restrict__ x, float* __restrict__ out) {
    int idx = blockIdx.x * blockDim.x + threadIdx.x;   // KS*16 threads
    int voxel = idx >> 4, dq = idx & 15;
    if (voxel >= g_M) return;
    int ukey = g_ukeys[voxel];
    int off = g_poff[ukey], cnt = g_pcount[ukey];
    float4 m = make_float4(NEG_INF, NEG_INF, NEG_INF, NEG_INF);
    for (int j = 0; j < cnt; j++) {
        int p = g_order[off + j];
        float4 v = ((const float4*)x)[p * 16 + dq];
        m.x = fmaxf(m.x, v.x); m.y = fmaxf(m.y, v.y);
        m.z = fmaxf(m.z, v.z); m.w = fmaxf(m.w, v.w);
    }
    ((float4*)out)[voxel * 16 + dq] = m;
}

__global__ void k_gather_pos(const float* __restrict__ pos, float* __restrict__ out, long out_size) {
    int voxel = blockIdx.x * blockDim.x + threadIdx.x;
    if (voxel >= g_M) return;
    int ukey = g_ukeys[voxel];
    int off = g_poff[ukey], cnt = g_pcount[ukey];
    float s0 = 0.f, s1 = 0.f, s2 = 0.f;
    for (int j = 0; j < cnt; j++) {
        int p = g_order[off + j];
        s0 += pos[p * 3 + 0]; s1 += pos[p * 3 + 1]; s2 += pos[p * 3 + 2];
    }
    float inv = 1.0f / (float)cnt;
    long o = (long)g_M * DD + (long)voxel * 3;
    if (o + 2 < out_size) { out[o] = s0 * inv; out[o + 1] = s1 * inv; out[o + 2] = s2 * inv; }
}

// 2 edges per thread (int4); gather pinv once, pack (u,v) for escatter reuse
__global__ void k_ecount(const int* __restrict__ ei, int E) {
    int e2 = blockIdx.x * blockDim.x + threadIdx.x;
    int e = e2 * 2;
    if (e >= E) return;
    int4 q = ((const int4*)ei)[e2];
    int u0 = g_pinv[q.x], v0 = g_pinv[q.y];
    g_euv[e] = ((ull)(unsigned)u0 << 32) | (unsigned)v0;
    if (u0 != v0) atomicAdd(&g_ucount[u0], 1);
    if (e + 1 < E) {
        int u1 = g_pinv[q.z], v1 = g_pinv[q.w];
        g_euv[e + 1] = ((ull)(unsigned)u1 << 32) | (unsigned)v1;
        if (u1 != v1) atomicAdd(&g_ucount[u1], 1);
    }
}

__global__ void k_escatter(int E) {
    int e = blockIdx.x * blockDim.x + threadIdx.x;
    if (e >= E) return;
    ull w = g_euv[e];
    int u = (int)(w >> 32), v = (int)(unsigned)w;
    if (u != v) {
        int p = g_uoff[u] + atomicAdd(&g_ucursor[u], 1);
        if (p < EMAX) g_vbuf[p] = v;
    }
}

__global__ void k_sortuniq() {
    int u = blockIdx.x * blockDim.x + threadIdx.x;
    if (u >= g_M) return;
    int len = g_ucount[u], base = g_uoff[u];
    for (int i = 1; i < len; i++) {
        int key = g_vbuf[base + i];
        int j = i - 1;
        while (j >= 0 && g_vbuf[base + j] > key) { g_vbuf[base + j + 1] = g_vbuf[base + j]; j--; }
        g_vbuf[base + j + 1] = key;
    }
    int c = 0, prev = -1;
    for (int i = 0; i < len; i++) {
        int v = g_vbuf[base + i];
        if (v != prev) { g_vbuf[base + c] = v; c++; prev = v; }
    }
    g_ucnt2[u] = c;
}

// warp per voxel: lanes stride over dedup'd v's
__global__ void k_write_edges(float* __restrict__ out, long out_size) {
    int gw = (blockIdx.x * blockDim.x + threadIdx.x) >> 5;
    int lane = threadIdx.x & 31;
    if (gw >= g_M) return;
    int c = g_ucnt2[gw];
    int base = g_uoff[gw];
    long wbase = (long)g_M * 67 + 2L * g_uoff2[gw];
    for (int i = lane; i < c; i += 32) {
        int v = g_vbuf[base + i];
        long w = wbase + 2L * i;
        if (w + 1 < out_size) { out[w] = (float)gw; out[w + 1] = (float)v; }
    }
}

__global__ void k_write_tail(float* __restrict__ out, long out_size) {
    int voxel = blockIdx.x * blockDim.x + threadIdx.x;
    int M = g_M, Eu = g_Eu;
    if (voxel >= M) return;
    long ebase = (long)M * 67;
    long o1 = ebase + 2L * (Eu + voxel);
    long o2 = ebase + 2L * (Eu + (long)M) + voxel;
    if (o1 + 1 < out_size) { out[o1] = (float)voxel; out[o1 + 1] = (float)voxel; }
    if (o2 < out_size) out[o2] = (float)(g_ukeys[voxel] >> 15);
}

// ---------------- streams/events (created once at program init; never during capture)
struct HxStreams {
    cudaStream_t s1, s2;
    cudaEvent_t fork, j1, j2;
    HxStreams() {
        cudaStreamCreateWithFlags(&s1, cudaStreamNonBlocking);
        cudaStreamCreateWithFlags(&s2, cudaStreamNonBlocking);
        cudaEventCreateWithFlags(&fork, cudaEventDisableTiming);
        cudaEventCreateWithFlags(&j1, cudaEventDisableTiming);
        cudaEventCreateWithFlags(&j2, cudaEventDisableTiming);
    }
};
static HxStreams g_hx;

// ---------------- launch ----------------
extern "C" void kernel_launch(void* const* d_in, const int* in_sizes, int n_in,
                              void* d_out, int out_size) {
    const float* x     = (const float*)d_in[0];
    const float* pos   = (const float*)d_in[1];
    const int*   ei    = (const int*)d_in[2];
    const int*   batch = (const int*)d_in[3];
    float*       out   = (float*)d_out;

    const int N = in_sizes[3];
    const int E = in_sizes[2] / 2;
    const long osz = (long)out_size;

    const int TB = 256;
    const int gN  = (N + TB - 1) / TB;
    const int gE  = (E + TB - 1) / TB;
    const int gE2 = (E / 2 + TB - 1) / TB;
    cudaStream_t s0 = 0;

    // front chain (everything depends on it)
    k_zero<<<KS / 4 / TB, TB, 0, s0>>>();
    k_key<<<gN, TB, 0, s0>>>(pos, batch, N);
    k_scan0<<<128, 1024, 0, s0>>>();
    k_porder<<<gN, TB, 0, s0>>>(N);

    // fork: gathers run concurrently with the edge chain
    cudaEventRecord(g_hx.fork, s0);
    cudaStreamWaitEvent(g_hx.s1, g_hx.fork, 0);
    cudaStreamWaitEvent(g_hx.s2, g_hx.fork, 0);
    k_gather_x<<<KS * 16 / TB, TB, 0, g_hx.s1>>>(x, out);
    k_gather_pos<<<KS / TB, TB, 0, g_hx.s2>>>(pos, out, osz);

    // edge chain on main stream
    k_ecount<<<gE2, TB, 0, s0>>>(ei, E);
    k_scan<<<128, 1024, 0, s0>>>(0);
    k_escatter<<<gE, TB, 0, s0>>>(E);
    k_sortuniq<<<KS / TB, TB, 0, s0>>>();
    k_scan<<<128, 1024, 0, s0>>>(1);
    k_write_edges<<<KS * 32 / TB, TB, 0, s0>>>(out, osz);
    k_write_tail<<<KS / TB, TB, 0, s0>>>(out, osz);

    // join
    cudaEventRecord(g_hx.j1, g_hx.s1);
    cudaEventRecord(g_hx.j2, g_hx.s2);
    cudaStreamWaitEvent(s0, g_hx.j1, 0);
    cudaStreamWaitEvent(s0, g_hx.j2, 0);
}